// round 3
// baseline (speedup 1.0000x reference)
#include <cuda_runtime.h>

#define NTOK 4096
#define EMB 512
#define NH 8
#define DH 64
#define QC 1536          // 3*EMB
#define SCALE 0.125f

// -------- scratch (device globals: no allocs allowed) --------
__device__ float g_qkv[NTOK * QC];              // 25.2 MB  qkv[n][j]
__device__ float g_Spart[64 * NH * DH * DH];    // 8.4 MB   split-K partials of K^T V
__device__ float g_qsum_part[64 * NH * DH];     // partials of sum_q Q
__device__ float g_S[NH * DH * DH];             // K_h^T V_h
__device__ float g_qsum[NH * DH];

// ============================================================
// K1: qkv[n][j] = sum_e x[e][n] * W[e][j] + b[j]
//   M=4096 (n), N=1536 (j), K=512 (e)
//   A = x laid out [K][M] (perfect for coalesced tile loads)
//   B = W laid out [K][N]
//   128x128x16 tiles, 256 threads, 8x8 per thread,
//   packed fp32x2 FMA (FFMA2) pairing adjacent output ROWS.
// ============================================================
__global__ __launch_bounds__(256) void k_qkv_gemm(
    const float* __restrict__ X, const float* __restrict__ W,
    const float* __restrict__ B)
{
    __shared__ float As[2][16][128];
    __shared__ float Bs[2][16][128];
    const int tid = threadIdx.x;
    const int bm = blockIdx.y * 128;
    const int bn = blockIdx.x * 128;
    const int ty = tid >> 4;            // 0..15
    const int tx = tid & 15;            // 0..15
    const int r = ty * 8;               // row offset in tile
    const int c = tx * 8;               // col offset in tile

    // two float4 load slots per operand per thread (512 slots of 16 tiles x 32 vecs)
    const int s0 = tid, s1 = tid + 256;
    const int ka0 = s0 >> 5, ma0 = (s0 & 31) * 4;
    const int ka1 = s1 >> 5, ma1 = (s1 & 31) * 4;

    unsigned long long acc[4][8];       // lane-lo = row r+2i, lane-hi = row r+2i+1
    #pragma unroll
    for (int i = 0; i < 4; i++)
        #pragma unroll
        for (int j = 0; j < 8; j++) acc[i][j] = 0ULL;

    // prefetch tile 0
    {
        float4 xa = *(const float4*)&X[ka0 * NTOK + bm + ma0];
        float4 xb = *(const float4*)&X[ka1 * NTOK + bm + ma1];
        float4 wa = *(const float4*)&W[ka0 * QC + bn + ma0];
        float4 wb = *(const float4*)&W[ka1 * QC + bn + ma1];
        *(float4*)&As[0][ka0][ma0] = xa;
        *(float4*)&As[0][ka1][ma1] = xb;
        *(float4*)&Bs[0][ka0][ma0] = wa;
        *(float4*)&Bs[0][ka1][ma1] = wb;
    }
    __syncthreads();

    for (int t = 0; t < 32; t++) {
        const int buf = t & 1;
        float4 xa, xb, wa, wb;
        if (t < 31) {
            const int k0 = (t + 1) * 16;
            xa = *(const float4*)&X[(k0 + ka0) * NTOK + bm + ma0];
            xb = *(const float4*)&X[(k0 + ka1) * NTOK + bm + ma1];
            wa = *(const float4*)&W[(k0 + ka0) * QC + bn + ma0];
            wb = *(const float4*)&W[(k0 + ka1) * QC + bn + ma1];
        }
        #pragma unroll
        for (int kk = 0; kk < 16; kk++) {
            unsigned long long a2[4];
            #pragma unroll
            for (int i = 0; i < 4; i++)   // LDS.64 of two adjacent rows (conflict-free)
                a2[i] = *(const unsigned long long*)&As[buf][kk][r + 2 * i];
            float4 b0 = *(const float4*)&Bs[buf][kk][c];
            float4 b1 = *(const float4*)&Bs[buf][kk][c + 4];
            unsigned int bu[8] = {
                __float_as_uint(b0.x), __float_as_uint(b0.y),
                __float_as_uint(b0.z), __float_as_uint(b0.w),
                __float_as_uint(b1.x), __float_as_uint(b1.y),
                __float_as_uint(b1.z), __float_as_uint(b1.w)};
            unsigned long long bd[8];
            #pragma unroll
            for (int j = 0; j < 8; j++)
                asm("mov.b64 %0, {%1, %2};" : "=l"(bd[j]) : "r"(bu[j]), "r"(bu[j]));
            #pragma unroll
            for (int i = 0; i < 4; i++)
                #pragma unroll
                for (int j = 0; j < 8; j++)
                    asm("fma.rn.f32x2 %0, %1, %2, %0;"
                        : "+l"(acc[i][j]) : "l"(a2[i]), "l"(bd[j]));
        }
        if (t < 31) {
            const int nb = buf ^ 1;
            *(float4*)&As[nb][ka0][ma0] = xa;
            *(float4*)&As[nb][ka1][ma1] = xb;
            *(float4*)&Bs[nb][ka0][ma0] = wa;
            *(float4*)&Bs[nb][ka1][ma1] = wb;
        }
        __syncthreads();
    }

    // epilogue: unpack, add bias, store
    float bias[8];
    #pragma unroll
    for (int j = 0; j < 8; j++) bias[j] = B[bn + c + j];
    #pragma unroll
    for (int i = 0; i < 4; i++) {
        float lo[8], hi[8];
        #pragma unroll
        for (int j = 0; j < 8; j++) {
            unsigned int l, h;
            asm("mov.b64 {%0, %1}, %2;" : "=r"(l), "=r"(h) : "l"(acc[i][j]));
            lo[j] = __uint_as_float(l) + bias[j];
            hi[j] = __uint_as_float(h) + bias[j];
        }
        float* o0 = &g_qkv[(bm + r + 2 * i) * QC + bn + c];
        float* o1 = o0 + QC;
        *(float4*)(o0)     = make_float4(lo[0], lo[1], lo[2], lo[3]);
        *(float4*)(o0 + 4) = make_float4(lo[4], lo[5], lo[6], lo[7]);
        *(float4*)(o1)     = make_float4(hi[0], hi[1], hi[2], hi[3]);
        *(float4*)(o1 + 4) = make_float4(hi[4], hi[5], hi[6], hi[7]);
    }
}

// ============================================================
// K2: split-K partials of S_h = K_h^T V_h and qsum_h.
//   grid (64 chunks, 8 heads), 256 threads. Chunk = 64 tokens.
// ============================================================
__global__ __launch_bounds__(256) void k_kv_outer()
{
    __shared__ float Ks[64][64];
    __shared__ float Vs[64][64];
    const int h = blockIdx.y;
    const int cidx = blockIdx.x;
    const int n0 = cidx * 64;
    const int tid = threadIdx.x;

    #pragma unroll
    for (int it = 0; it < 4; it++) {
        int s = tid + it * 256;          // 0..1023 float4 slots
        int n = s >> 4, dv = (s & 15) * 4;
        const float* row = &g_qkv[(n0 + n) * QC + h * DH];
        *(float4*)&Ks[n][dv] = *(const float4*)(row + EMB + dv);
        *(float4*)&Vs[n][dv] = *(const float4*)(row + 2 * EMB + dv);
    }
    __syncthreads();

    const int ty = tid >> 4, tx = tid & 15;
    const int d1 = ty * 4, d2 = tx * 4;
    float acc[4][4] = {};
    for (int n = 0; n < 64; n++) {
        float a[4], b[4];
        #pragma unroll
        for (int i = 0; i < 4; i++) a[i] = Ks[n][d1 + i];
        #pragma unroll
        for (int j = 0; j < 4; j++) b[j] = Vs[n][d2 + j];
        #pragma unroll
        for (int i = 0; i < 4; i++)
            #pragma unroll
            for (int j = 0; j < 4; j++)
                acc[i][j] += a[i] * b[j];
    }
    float* Sout = &g_Spart[cidx * (NH * DH * DH) + h * (DH * DH)];
    #pragma unroll
    for (int i = 0; i < 4; i++)
        *(float4*)&Sout[(d1 + i) * DH + d2] =
            make_float4(acc[i][0], acc[i][1], acc[i][2], acc[i][3]);

    if (tid < 64) {
        float s = 0.f;
        for (int n = 0; n < 64; n++)
            s += g_qkv[(n0 + n) * QC + h * DH + tid];
        g_qsum_part[cidx * (NH * DH) + h * DH + tid] = s;
    }
}

// ============================================================
// K2b: deterministic reduction of partials.
// ============================================================
__global__ __launch_bounds__(256) void k_reduce()
{
    int idx = blockIdx.x * 256 + threadIdx.x;   // grid 130 -> 33280 threads
    if (idx < NH * DH * DH) {
        float s = 0.f;
        #pragma unroll 8
        for (int c = 0; c < 64; c++) s += g_Spart[c * (NH * DH * DH) + idx];
        g_S[idx] = s;
    } else if (idx < NH * DH * DH + NH * DH) {
        int o = idx - NH * DH * DH;
        float s = 0.f;
        #pragma unroll 8
        for (int c = 0; c < 64; c++) s += g_qsum_part[c * (NH * DH) + o];
        g_qsum[o] = s;
    }
}

// ============================================================
// K3: output[h][n][d] = SCALE * sum_d' Q[n,h,d'] * S_h[d'][d]
//   grid (64 n-tiles of 64 rows, 8 heads), 256 threads, 2x8/thread.
// ============================================================
__global__ __launch_bounds__(256) void k_out_gemm(float* __restrict__ out)
{
    __shared__ float Ss[64 * 64];
    __shared__ float Qs[64 * 68];      // pad 68: conflict-free column reads, 16B-aligned f4 stores
    const int h = blockIdx.y;
    const int n0 = blockIdx.x * 64;
    const int tid = threadIdx.x;

    #pragma unroll
    for (int it = 0; it < 4; it++) {
        int s = tid + it * 256;        // 0..1023 f4 slots of S
        *(float4*)&Ss[s * 4] = *(const float4*)&g_S[h * (DH * DH) + s * 4];
    }
    #pragma unroll
    for (int it = 0; it < 4; it++) {
        int s = tid + it * 256;        // 0..1023 f4 slots of Q (64 rows x 16 vecs)
        int n = s >> 4, dv = (s & 15) * 4;
        *(float4*)&Qs[n * 68 + dv] =
            *(const float4*)&g_qkv[(n0 + n) * QC + h * DH + dv];
    }
    __syncthreads();

    const int ty = tid >> 3;           // 0..31
    const int tx = tid & 7;            // 0..7
    const int r = ty * 2, c = tx * 8;
    float acc[2][8] = {};
    for (int dk = 0; dk < 64; dk++) {
        float a0 = Qs[(r + 0) * 68 + dk];
        float a1 = Qs[(r + 1) * 68 + dk];
        float4 b0 = *(const float4*)&Ss[dk * 64 + c];
        float4 b1 = *(const float4*)&Ss[dk * 64 + c + 4];
        float bv[8] = {b0.x, b0.y, b0.z, b0.w, b1.x, b1.y, b1.z, b1.w};
        #pragma unroll
        for (int j = 0; j < 8; j++) {
            acc[0][j] += a0 * bv[j];
            acc[1][j] += a1 * bv[j];
        }
    }
    #pragma unroll
    for (int i = 0; i < 2; i++) {
        float* o = out + (NH * NTOK) + h * (NTOK * DH) + (n0 + r + i) * DH + c;
        *(float4*)(o)     = make_float4(acc[i][0] * SCALE, acc[i][1] * SCALE,
                                        acc[i][2] * SCALE, acc[i][3] * SCALE);
        *(float4*)(o + 4) = make_float4(acc[i][4] * SCALE, acc[i][5] * SCALE,
                                        acc[i][6] * SCALE, acc[i][7] * SCALE);
    }
}

// ============================================================
// K4: coarse[h][n] = SCALE * dot(K[n,h,:], qsum[h,:])
// ============================================================
__global__ __launch_bounds__(256) void k_coarse(float* __restrict__ out)
{
    int idx = blockIdx.x * 256 + threadIdx.x;   // 128 blocks -> 32768 threads
    int h = idx >> 12, n = idx & (NTOK - 1);
    const float4* kp = (const float4*)&g_qkv[n * QC + EMB + h * DH];
    const float4* qp = (const float4*)&g_qsum[h * DH];
    float s = 0.f;
    #pragma unroll
    for (int v = 0; v < 16; v++) {
        float4 a = kp[v], b = qp[v];
        s += a.x * b.x + a.y * b.y + a.z * b.z + a.w * b.w;
    }
    out[idx] = s * SCALE;
}

// ============================================================
extern "C" void kernel_launch(void* const* d_in, const int* in_sizes, int n_in,
                              void* d_out, int out_size)
{
    const float* x = (const float*)d_in[0];   // [512][4096] (E-major)
    const float* W = (const float*)d_in[1];   // [512][1536]
    const float* b = (const float*)d_in[2];   // [1536]
    float* out = (float*)d_out;               // [32768 coarse][2097152 output]

    k_qkv_gemm<<<dim3(12, 32), 256>>>(x, W, b);
    k_kv_outer<<<dim3(64, 8), 256>>>();
    k_reduce<<<130, 256>>>();
    k_out_gemm<<<dim3(64, 8), 256>>>(out);
    k_coarse<<<128, 256>>>(out);
}

// round 5
// speedup vs baseline: 1.3340x; 1.3340x over previous
#include <cuda_runtime.h>
#include <cuda_bf16.h>
#include <cstdint>

#define NTOK 4096
#define EMB 512
#define NH 8
#define DH 64
#define QC 1536          // 3*EMB
#define SCALE 0.125f

// -------- scratch (device globals: no allocs allowed) --------
__device__ float g_qkv[NTOK * QC];                         // qkv[n][j]
__device__ float g_Spart[64 * NH * DH * DH];               // split-K partials of K^T V
__device__ float g_qsum_part[64 * NH * DH];
__device__ float g_S[NH * DH * DH];
__device__ float g_qsum[NH * DH];
// bf16 split operands, K-major [row][k=512]
__device__ __align__(1024) __nv_bfloat16 g_Ahi[NTOK * EMB];
__device__ __align__(1024) __nv_bfloat16 g_Alo[NTOK * EMB];
__device__ __align__(1024) __nv_bfloat16 g_Bhi[QC * EMB];
__device__ __align__(1024) __nv_bfloat16 g_Blo[QC * EMB];

// ---------------- helpers ----------------
__device__ __forceinline__ uint32_t smem_u32(const void* p) {
    uint32_t a;
    asm("{ .reg .u64 t; cvta.to.shared.u64 t, %1; cvt.u32.u64 %0, t; }" : "=r"(a) : "l"(p));
    return a;
}
// 16B-chunk XOR swizzle inside a 128x32 bf16 tile (row stride 64B, 4 chunks/row)
__device__ __forceinline__ uint32_t swz(uint32_t row, uint32_t cv) {
    return row * 64u + ((cv ^ ((row >> 1) & 3u)) << 4);
}
__device__ __forceinline__ void ldsm4(uint32_t& r0, uint32_t& r1, uint32_t& r2,
                                      uint32_t& r3, uint32_t addr) {
    asm volatile("ldmatrix.sync.aligned.m8n8.x4.shared.b16 {%0,%1,%2,%3}, [%4];"
                 : "=r"(r0), "=r"(r1), "=r"(r2), "=r"(r3) : "r"(addr));
}
__device__ __forceinline__ void mma16816(float* c, const uint32_t* a, uint32_t b0, uint32_t b1) {
    asm volatile("mma.sync.aligned.m16n8k16.row.col.f32.bf16.bf16.f32 "
                 "{%0,%1,%2,%3}, {%4,%5,%6,%7}, {%8,%9}, {%0,%1,%2,%3};"
                 : "+f"(c[0]), "+f"(c[1]), "+f"(c[2]), "+f"(c[3])
                 : "r"(a[0]), "r"(a[1]), "r"(a[2]), "r"(a[3]), "r"(b0), "r"(b1));
}

// ============================================================
// split kernels: fp32 [K][M] -> bf16 hi/lo [M][K]
// ============================================================
__global__ __launch_bounds__(256) void k_splitX(const float* __restrict__ X)
{
    __shared__ float t[32][33];
    const int m0 = blockIdx.x * 32, k0 = blockIdx.y * 32;
    const int tx = threadIdx.x & 31, ty = threadIdx.x >> 5;   // 32 x 8
    #pragma unroll
    for (int j = 0; j < 4; j++)
        t[ty + 8 * j][tx] = X[(k0 + ty + 8 * j) * NTOK + m0 + tx];
    __syncthreads();
    #pragma unroll
    for (int j = 0; j < 4; j++) {
        float v = t[tx][ty + 8 * j];
        __nv_bfloat16 h = __float2bfloat16_rn(v);
        __nv_bfloat16 l = __float2bfloat16_rn(v - __bfloat162float(h));
        int idx = (m0 + ty + 8 * j) * EMB + k0 + tx;
        g_Ahi[idx] = h; g_Alo[idx] = l;
    }
}
__global__ __launch_bounds__(256) void k_splitW(const float* __restrict__ W)
{
    __shared__ float t[32][33];
    const int n0 = blockIdx.x * 32, k0 = blockIdx.y * 32;
    const int tx = threadIdx.x & 31, ty = threadIdx.x >> 5;
    #pragma unroll
    for (int j = 0; j < 4; j++)
        t[ty + 8 * j][tx] = W[(k0 + ty + 8 * j) * QC + n0 + tx];
    __syncthreads();
    #pragma unroll
    for (int j = 0; j < 4; j++) {
        float v = t[tx][ty + 8 * j];
        __nv_bfloat16 h = __float2bfloat16_rn(v);
        __nv_bfloat16 l = __float2bfloat16_rn(v - __bfloat162float(h));
        int idx = (n0 + ty + 8 * j) * EMB + k0 + tx;
        g_Bhi[idx] = h; g_Blo[idx] = l;
    }
}

// ============================================================
// K1: mma.sync bf16 3-product GEMM (HMMA).
//   CTA 128x128, 8 warps (2m x 4n), warp tile 64x32, K chunks of 32,
//   2-stage cp.async pipeline, swizzled smem, shared fp32 accumulators.
// ============================================================
#define TILE_B 8192                 // one 128x32 bf16 tile
#define STAGE_B (4 * TILE_B)        // Ahi, Alo, Bhi, Blo
#define QTC_SMEM (2 * STAGE_B + 256)

__device__ __forceinline__ void load_stage(int s, uint32_t base, int bm, int bn, int tid)
{
    const int k0 = s * 32;
    const __nv_bfloat16* srcs[4] = {
        g_Ahi + (size_t)bm * EMB, g_Alo + (size_t)bm * EMB,
        g_Bhi + (size_t)bn * EMB, g_Blo + (size_t)bn * EMB };
    #pragma unroll
    for (int tile = 0; tile < 4; tile++) {
        #pragma unroll
        for (int t = 0; t < 2; t++) {
            int q = tid + t * 256;            // 0..511
            int row = q >> 2, cv = q & 3;
            const __nv_bfloat16* src = srcs[tile] + (size_t)row * EMB + k0 + cv * 8;
            uint32_t dst = base + tile * TILE_B + swz(row, cv);
            asm volatile("cp.async.cg.shared.global [%0], [%1], 16;"
                         :: "r"(dst), "l"(src));
        }
    }
    asm volatile("cp.async.commit_group;" ::: "memory");
}

__global__ __launch_bounds__(256, 2) void k_qkv_tc(const float* __restrict__ bias)
{
    extern __shared__ char dsm[];
    __shared__ float biasS[128];
    const uint32_t stage0 = (smem_u32(dsm) + 127u) & ~127u;
    const int tid = threadIdx.x, wid = tid >> 5, lane = tid & 31;
    const int wm = wid >> 2, wn = wid & 3;               // warp grid 2 x 4
    const int bm = blockIdx.y * 128, bn = blockIdx.x * 128;

    if (tid < 128) biasS[tid] = bias[bn + tid];

    float acc[4][4][4];                                   // [m-sub][n-sub][c0..c3]
    #pragma unroll
    for (int i = 0; i < 4; i++)
        #pragma unroll
        for (int j = 0; j < 4; j++)
            #pragma unroll
            for (int c = 0; c < 4; c++) acc[i][j][c] = 0.f;

    // ldmatrix lane-address components (constant per thread)
    const int a_row = wm * 64 + ((lane >> 3) & 1) * 8 + (lane & 7);
    const int a_kh  = (lane >> 4) & 1;
    const int b_row = wn * 32 + ((lane >> 4) & 1) * 8 + (lane & 7);
    const int b_kh  = (lane >> 3) & 1;

    load_stage(0, stage0, bm, bn, tid);
    load_stage(1, stage0 + STAGE_B, bm, bn, tid);

    for (int s = 0; s < 16; s++) {
        if (s < 15) asm volatile("cp.async.wait_group 1;" ::: "memory");
        else        asm volatile("cp.async.wait_group 0;" ::: "memory");
        __syncthreads();
        const uint32_t buf = stage0 + (uint32_t)(s & 1) * STAGE_B;
        const uint32_t tAhi = buf, tAlo = buf + TILE_B;
        const uint32_t tBhi = buf + 2 * TILE_B, tBlo = buf + 3 * TILE_B;

        #pragma unroll
        for (int ks = 0; ks < 2; ks++) {
            const int a_cv = 2 * ks + a_kh;
            const int b_cv = 2 * ks + b_kh;
            uint32_t bh[8], bl[8];
            #pragma unroll
            for (int p = 0; p < 2; p++) {
                uint32_t ba = swz((uint32_t)(b_row + p * 16), (uint32_t)b_cv);
                ldsm4(bh[p * 4], bh[p * 4 + 1], bh[p * 4 + 2], bh[p * 4 + 3], tBhi + ba);
                ldsm4(bl[p * 4], bl[p * 4 + 1], bl[p * 4 + 2], bl[p * 4 + 3], tBlo + ba);
            }
            uint32_t a[4][4];
            #pragma unroll
            for (int i = 0; i < 4; i++) {
                uint32_t aa = swz((uint32_t)(a_row + i * 16), (uint32_t)a_cv);
                ldsm4(a[i][0], a[i][1], a[i][2], a[i][3], tAhi + aa);
            }
            #pragma unroll
            for (int i = 0; i < 4; i++)
                #pragma unroll
                for (int j = 0; j < 4; j++) {
                    mma16816(acc[i][j], a[i], bh[(j >> 1) * 4 + (j & 1) * 2],
                                              bh[(j >> 1) * 4 + (j & 1) * 2 + 1]);
                    mma16816(acc[i][j], a[i], bl[(j >> 1) * 4 + (j & 1) * 2],
                                              bl[(j >> 1) * 4 + (j & 1) * 2 + 1]);
                }
            #pragma unroll
            for (int i = 0; i < 4; i++) {
                uint32_t aa = swz((uint32_t)(a_row + i * 16), (uint32_t)a_cv);
                ldsm4(a[i][0], a[i][1], a[i][2], a[i][3], tAlo + aa);
            }
            #pragma unroll
            for (int i = 0; i < 4; i++)
                #pragma unroll
                for (int j = 0; j < 4; j++)
                    mma16816(acc[i][j], a[i], bh[(j >> 1) * 4 + (j & 1) * 2],
                                              bh[(j >> 1) * 4 + (j & 1) * 2 + 1]);
        }
        __syncthreads();
        if (s + 2 < 16)
            load_stage(s + 2, stage0 + (uint32_t)(s & 1) * STAGE_B, bm, bn, tid);
    }

    // epilogue: c0..c3 = (g,2t),(g,2t+1),(g+8,2t),(g+8,2t+1)
    const int g = lane >> 2, t2 = (lane & 3) * 2;
    #pragma unroll
    for (int i = 0; i < 4; i++) {
        const int row0 = bm + wm * 64 + i * 16 + g;
        #pragma unroll
        for (int j = 0; j < 4; j++) {
            const int colL = wn * 32 + j * 8 + t2;        // local col in [0,128)
            const int col = bn + colL;
            float2 v0 = { acc[i][j][0] + biasS[colL], acc[i][j][1] + biasS[colL + 1] };
            float2 v1 = { acc[i][j][2] + biasS[colL], acc[i][j][3] + biasS[colL + 1] };
            *(float2*)&g_qkv[(size_t)row0 * QC + col] = v0;
            *(float2*)&g_qkv[(size_t)(row0 + 8) * QC + col] = v1;
        }
    }
}

// ============================================================
// K2: split-K partials of S_h = K_h^T V_h and qsum_h
// ============================================================
__global__ __launch_bounds__(256) void k_kv_outer()
{
    __shared__ float Ks[64][64];
    __shared__ float Vs[64][64];
    const int h = blockIdx.y;
    const int cidx = blockIdx.x;
    const int n0 = cidx * 64;
    const int tid = threadIdx.x;

    #pragma unroll
    for (int it = 0; it < 4; it++) {
        int s = tid + it * 256;
        int n = s >> 4, dv = (s & 15) * 4;
        const float* row = &g_qkv[(n0 + n) * QC + h * DH];
        *(float4*)&Ks[n][dv] = *(const float4*)(row + EMB + dv);
        *(float4*)&Vs[n][dv] = *(const float4*)(row + 2 * EMB + dv);
    }
    __syncthreads();

    const int ty = tid >> 4, tx = tid & 15;
    const int d1 = ty * 4, d2 = tx * 4;
    float acc[4][4] = {};
    for (int n = 0; n < 64; n++) {
        float a[4], b[4];
        #pragma unroll
        for (int i = 0; i < 4; i++) a[i] = Ks[n][d1 + i];
        #pragma unroll
        for (int j = 0; j < 4; j++) b[j] = Vs[n][d2 + j];
        #pragma unroll
        for (int i = 0; i < 4; i++)
            #pragma unroll
            for (int j = 0; j < 4; j++)
                acc[i][j] += a[i] * b[j];
    }
    float* Sout = &g_Spart[cidx * (NH * DH * DH) + h * (DH * DH)];
    #pragma unroll
    for (int i = 0; i < 4; i++)
        *(float4*)&Sout[(d1 + i) * DH + d2] =
            make_float4(acc[i][0], acc[i][1], acc[i][2], acc[i][3]);

    if (tid < 64) {
        float s = 0.f;
        for (int n = 0; n < 64; n++)
            s += g_qkv[(n0 + n) * QC + h * DH + tid];
        g_qsum_part[cidx * (NH * DH) + h * DH + tid] = s;
    }
}

__global__ __launch_bounds__(256) void k_reduce()
{
    int idx = blockIdx.x * 256 + threadIdx.x;
    if (idx < NH * DH * DH) {
        float s = 0.f;
        #pragma unroll 8
        for (int c = 0; c < 64; c++) s += g_Spart[c * (NH * DH * DH) + idx];
        g_S[idx] = s;
    } else if (idx < NH * DH * DH + NH * DH) {
        int o = idx - NH * DH * DH;
        float s = 0.f;
        #pragma unroll 8
        for (int c = 0; c < 64; c++) s += g_qsum_part[c * (NH * DH) + o];
        g_qsum[o] = s;
    }
}

// ============================================================
// K3: output = SCALE * Q @ S_h, 128-row tiles, transposed-Q smem,
//     8 rows x 4 cols per thread, row-paired fp32x2 FMA.
// ============================================================
__global__ __launch_bounds__(256) void k_out_gemm(float* __restrict__ out)
{
    __shared__ float Ss[64 * 64];       // [dk][d]
    __shared__ float Qt[64 * 128];      // [dk][n] transposed
    const int h = blockIdx.y;
    const int n0 = blockIdx.x * 128;
    const int tid = threadIdx.x;

    #pragma unroll
    for (int it = 0; it < 4; it++) {
        int s = tid + it * 256;
        *(float4*)&Ss[s * 4] = *(const float4*)&g_S[h * (DH * DH) + s * 4];
    }
    #pragma unroll
    for (int it = 0; it < 8; it++) {
        int s = tid + it * 256;          // 2048 slots: n(128) x dv4(16)
        int n = s & 127, d0 = (s >> 7) * 4;
        float4 v = *(const float4*)&g_qkv[(size_t)(n0 + n) * QC + h * DH + d0];
        Qt[(d0 + 0) * 128 + n] = v.x;
        Qt[(d0 + 1) * 128 + n] = v.y;
        Qt[(d0 + 2) * 128 + n] = v.z;
        Qt[(d0 + 3) * 128 + n] = v.w;
    }
    __syncthreads();

    const int ty = tid >> 4, tx = tid & 15;
    const int r0 = ty * 8, c0 = tx * 4;
    unsigned long long acc[4][4];
    #pragma unroll
    for (int i = 0; i < 4; i++)
        #pragma unroll
        for (int j = 0; j < 4; j++) acc[i][j] = 0ULL;

    #pragma unroll 4
    for (int k = 0; k < 64; k++) {
        unsigned long long a2[4];
        #pragma unroll
        for (int i = 0; i < 4; i++)
            a2[i] = *(const unsigned long long*)&Qt[k * 128 + r0 + 2 * i];
        float4 b = *(const float4*)&Ss[k * 64 + c0];
        unsigned int bu[4] = { __float_as_uint(b.x), __float_as_uint(b.y),
                               __float_as_uint(b.z), __float_as_uint(b.w) };
        unsigned long long bd[4];
        #pragma unroll
        for (int j = 0; j < 4; j++)
            asm("mov.b64 %0, {%1, %2};" : "=l"(bd[j]) : "r"(bu[j]), "r"(bu[j]));
        #pragma unroll
        for (int i = 0; i < 4; i++)
            #pragma unroll
            for (int j = 0; j < 4; j++)
                asm("fma.rn.f32x2 %0, %1, %2, %0;"
                    : "+l"(acc[i][j]) : "l"(a2[i]), "l"(bd[j]));
    }

    #pragma unroll
    for (int i = 0; i < 4; i++) {
        float lo[4], hi[4];
        #pragma unroll
        for (int j = 0; j < 4; j++) {
            unsigned int l, hb;
            asm("mov.b64 {%0, %1}, %2;" : "=r"(l), "=r"(hb) : "l"(acc[i][j]));
            lo[j] = __uint_as_float(l) * SCALE;
            hi[j] = __uint_as_float(hb) * SCALE;
        }
        float* o0 = out + (NH * NTOK) + h * (NTOK * DH)
                  + (size_t)(n0 + r0 + 2 * i) * DH + c0;
        *(float4*)(o0)      = make_float4(lo[0], lo[1], lo[2], lo[3]);
        *(float4*)(o0 + DH) = make_float4(hi[0], hi[1], hi[2], hi[3]);
    }
}

// ============================================================
// K4: coarse[h][n] = SCALE * dot(K[n,h,:], qsum[h,:])
// ============================================================
__global__ __launch_bounds__(256) void k_coarse(float* __restrict__ out)
{
    int idx = blockIdx.x * 256 + threadIdx.x;
    int h = idx >> 12, n = idx & (NTOK - 1);
    const float4* kp = (const float4*)&g_qkv[n * QC + EMB + h * DH];
    const float4* qp = (const float4*)&g_qsum[h * DH];
    float s = 0.f;
    #pragma unroll
    for (int v = 0; v < 16; v++) {
        float4 a = kp[v], b = qp[v];
        s += a.x * b.x + a.y * b.y + a.z * b.z + a.w * b.w;
    }
    out[idx] = s * SCALE;
}

// ============================================================
extern "C" void kernel_launch(void* const* d_in, const int* in_sizes, int n_in,
                              void* d_out, int out_size)
{
    const float* x = (const float*)d_in[0];   // [512][4096]
    const float* W = (const float*)d_in[1];   // [512][1536]
    const float* b = (const float*)d_in[2];   // [1536]
    float* out = (float*)d_out;               // [32768 coarse][2097152 output]

    static bool attr_done = false;
    if (!attr_done) {
        cudaFuncSetAttribute(k_qkv_tc, cudaFuncAttributeMaxDynamicSharedMemorySize, QTC_SMEM);
        attr_done = true;
    }

    k_splitX<<<dim3(128, 16), 256>>>(x);
    k_splitW<<<dim3(48, 16), 256>>>(W);
    k_qkv_tc<<<dim3(12, 32), 256, QTC_SMEM>>>(b);
    k_kv_outer<<<dim3(64, 8), 256>>>();
    k_reduce<<<130, 256>>>();
    k_out_gemm<<<dim3(32, 8), 256>>>(out);
    k_coarse<<<128, 256>>>(out);
}

// round 6
// speedup vs baseline: 1.9547x; 1.4653x over previous
#include <cuda_runtime.h>
#include <cuda_bf16.h>
#include <cstdint>

#define NTOK 4096
#define EMB 512
#define NH 8
#define DH 64
#define QC 1536          // 3*EMB
#define SCALE 0.125f

// -------- scratch (device globals: no allocs allowed) --------
__device__ float g_qkv[NTOK * QC];                         // qkv[n][j]
__device__ float g_Spart[64 * NH * DH * DH];               // split-K partials of K^T V
__device__ float g_qsum_part[64 * NH * DH];                // [chunk][d] partial col-sums of Q
__device__ float g_S[NH * DH * DH];
__device__ float g_qsum[NH * DH];
// bf16 split operands, K-major [row][k=512]
__device__ __align__(1024) __nv_bfloat16 g_Ahi[NTOK * EMB];
__device__ __align__(1024) __nv_bfloat16 g_Alo[NTOK * EMB];
__device__ __align__(1024) __nv_bfloat16 g_Bhi[QC * EMB];
__device__ __align__(1024) __nv_bfloat16 g_Blo[QC * EMB];

// ---------------- helpers ----------------
__device__ __forceinline__ uint32_t smem_u32(const void* p) {
    uint32_t a;
    asm("{ .reg .u64 t; cvta.to.shared.u64 t, %1; cvt.u32.u64 %0, t; }" : "=r"(a) : "l"(p));
    return a;
}
// 16B-chunk XOR swizzle inside an Nx32 bf16 tile (row stride 64B, 4 chunks/row)
__device__ __forceinline__ uint32_t swz(uint32_t row, uint32_t cv) {
    return row * 64u + ((cv ^ ((row >> 1) & 3u)) << 4);
}
__device__ __forceinline__ void ldsm4(uint32_t& r0, uint32_t& r1, uint32_t& r2,
                                      uint32_t& r3, uint32_t addr) {
    asm volatile("ldmatrix.sync.aligned.m8n8.x4.shared.b16 {%0,%1,%2,%3}, [%4];"
                 : "=r"(r0), "=r"(r1), "=r"(r2), "=r"(r3) : "r"(addr));
}
__device__ __forceinline__ void mma16816(float* c, const uint32_t* a, uint32_t b0, uint32_t b1) {
    asm volatile("mma.sync.aligned.m16n8k16.row.col.f32.bf16.bf16.f32 "
                 "{%0,%1,%2,%3}, {%4,%5,%6,%7}, {%8,%9}, {%0,%1,%2,%3};"
                 : "+f"(c[0]), "+f"(c[1]), "+f"(c[2]), "+f"(c[3])
                 : "r"(a[0]), "r"(a[1]), "r"(a[2]), "r"(a[3]), "r"(b0), "r"(b1));
}

// ============================================================
// split kernels: fp32 [K][M] -> bf16 hi/lo [M][K]
// ============================================================
__global__ __launch_bounds__(256) void k_splitX(const float* __restrict__ X)
{
    __shared__ float t[32][33];
    const int m0 = blockIdx.x * 32, k0 = blockIdx.y * 32;
    const int tx = threadIdx.x & 31, ty = threadIdx.x >> 5;   // 32 x 8
    #pragma unroll
    for (int j = 0; j < 4; j++)
        t[ty + 8 * j][tx] = X[(k0 + ty + 8 * j) * NTOK + m0 + tx];
    __syncthreads();
    #pragma unroll
    for (int j = 0; j < 4; j++) {
        float v = t[tx][ty + 8 * j];
        __nv_bfloat16 h = __float2bfloat16_rn(v);
        __nv_bfloat16 l = __float2bfloat16_rn(v - __bfloat162float(h));
        int idx = (m0 + ty + 8 * j) * EMB + k0 + tx;
        g_Ahi[idx] = h; g_Alo[idx] = l;
    }
}
__global__ __launch_bounds__(256) void k_splitW(const float* __restrict__ W)
{
    __shared__ float t[32][33];
    const int n0 = blockIdx.x * 32, k0 = blockIdx.y * 32;
    const int tx = threadIdx.x & 31, ty = threadIdx.x >> 5;
    #pragma unroll
    for (int j = 0; j < 4; j++)
        t[ty + 8 * j][tx] = W[(k0 + ty + 8 * j) * QC + n0 + tx];
    __syncthreads();
    #pragma unroll
    for (int j = 0; j < 4; j++) {
        float v = t[tx][ty + 8 * j];
        __nv_bfloat16 h = __float2bfloat16_rn(v);
        __nv_bfloat16 l = __float2bfloat16_rn(v - __bfloat162float(h));
        int idx = (n0 + ty + 8 * j) * EMB + k0 + tx;
        g_Bhi[idx] = h; g_Blo[idx] = l;
    }
}

// ============================================================
// K1: mma.sync bf16 3-product GEMM (HMMA).
//   CTA 64x128, 8 warps (2m x 4n), warp tile 32x32, K chunks of 32,
//   3-stage cp.async pipeline (single __syncthreads per K-step).
// ============================================================
#define A_TILE_B 4096               // 64x32 bf16
#define B_TILE_B 8192               // 128x32 bf16
#define OFF_ALO  4096
#define OFF_BHI  8192
#define OFF_BLO  16384
#define STAGE_B  24576              // Ahi, Alo, Bhi, Blo
#define NSTAGE   3
#define QTC_SMEM (NSTAGE * STAGE_B + 256)

__device__ __forceinline__ void load_stage(int s, uint32_t base, int bm, int bn, int tid)
{
    const int k0 = s * 32;
    // A tiles: 64 rows x 4 chunks = 256 -> one pass
    {
        int row = tid >> 2, cv = tid & 3;
        size_t off = (size_t)(bm + row) * EMB + k0 + cv * 8;
        uint32_t o = base + swz((uint32_t)row, (uint32_t)cv);
        asm volatile("cp.async.cg.shared.global [%0], [%1], 16;"
                     :: "r"(o), "l"(g_Ahi + off));
        asm volatile("cp.async.cg.shared.global [%0], [%1], 16;"
                     :: "r"(o + OFF_ALO), "l"(g_Alo + off));
    }
    // B tiles: 128 rows x 4 chunks = 512 -> two passes
    #pragma unroll
    for (int t = 0; t < 2; t++) {
        int q = tid + t * 256;
        int row = q >> 2, cv = q & 3;
        size_t off = (size_t)(bn + row) * EMB + k0 + cv * 8;
        uint32_t o = base + swz((uint32_t)row, (uint32_t)cv);
        asm volatile("cp.async.cg.shared.global [%0], [%1], 16;"
                     :: "r"(o + OFF_BHI), "l"(g_Bhi + off));
        asm volatile("cp.async.cg.shared.global [%0], [%1], 16;"
                     :: "r"(o + OFF_BLO), "l"(g_Blo + off));
    }
    asm volatile("cp.async.commit_group;" ::: "memory");
}

__global__ __launch_bounds__(256, 2) void k_qkv_tc(const float* __restrict__ bias)
{
    extern __shared__ char dsm[];
    __shared__ float biasS[128];
    const uint32_t stage0 = (smem_u32(dsm) + 127u) & ~127u;
    const int tid = threadIdx.x, wid = tid >> 5, lane = tid & 31;
    const int wm = wid >> 2, wn = wid & 3;               // warp grid 2m x 4n
    const int bm = blockIdx.y * 64, bn = blockIdx.x * 128;

    if (tid < 128) biasS[tid] = bias[bn + tid];

    float acc[2][4][4];                                   // [m-sub][n-sub][c]
    #pragma unroll
    for (int i = 0; i < 2; i++)
        #pragma unroll
        for (int j = 0; j < 4; j++)
            #pragma unroll
            for (int c = 0; c < 4; c++) acc[i][j][c] = 0.f;

    const int a_row = wm * 32 + ((lane >> 3) & 1) * 8 + (lane & 7);
    const int a_kh  = (lane >> 4) & 1;
    const int b_row = wn * 32 + ((lane >> 4) & 1) * 8 + (lane & 7);
    const int b_kh  = (lane >> 3) & 1;

    load_stage(0, stage0, bm, bn, tid);
    load_stage(1, stage0 + STAGE_B, bm, bn, tid);

    for (int s = 0; s < 16; s++) {
        if (s < 15) asm volatile("cp.async.wait_group 1;" ::: "memory");
        else        asm volatile("cp.async.wait_group 0;" ::: "memory");
        __syncthreads();
        const uint32_t buf = stage0 + (uint32_t)(s % NSTAGE) * STAGE_B;
        const uint32_t tAhi = buf, tAlo = buf + OFF_ALO;
        const uint32_t tBhi = buf + OFF_BHI, tBlo = buf + OFF_BLO;

        #pragma unroll
        for (int ks = 0; ks < 2; ks++) {
            const int a_cv = 2 * ks + a_kh;
            const int b_cv = 2 * ks + b_kh;
            uint32_t bh[8], bl[8];
            #pragma unroll
            for (int p = 0; p < 2; p++) {
                uint32_t ba = swz((uint32_t)(b_row + p * 16), (uint32_t)b_cv);
                ldsm4(bh[p * 4], bh[p * 4 + 1], bh[p * 4 + 2], bh[p * 4 + 3], tBhi + ba);
                ldsm4(bl[p * 4], bl[p * 4 + 1], bl[p * 4 + 2], bl[p * 4 + 3], tBlo + ba);
            }
            uint32_t a[2][4];
            #pragma unroll
            for (int i = 0; i < 2; i++) {
                uint32_t aa = swz((uint32_t)(a_row + i * 16), (uint32_t)a_cv);
                ldsm4(a[i][0], a[i][1], a[i][2], a[i][3], tAhi + aa);
            }
            #pragma unroll
            for (int i = 0; i < 2; i++)
                #pragma unroll
                for (int j = 0; j < 4; j++) {
                    mma16816(acc[i][j], a[i], bh[j * 2], bh[j * 2 + 1]);
                    mma16816(acc[i][j], a[i], bl[j * 2], bl[j * 2 + 1]);
                }
            #pragma unroll
            for (int i = 0; i < 2; i++) {
                uint32_t aa = swz((uint32_t)(a_row + i * 16), (uint32_t)a_cv);
                ldsm4(a[i][0], a[i][1], a[i][2], a[i][3], tAlo + aa);
            }
            #pragma unroll
            for (int i = 0; i < 2; i++)
                #pragma unroll
                for (int j = 0; j < 4; j++)
                    mma16816(acc[i][j], a[i], bh[j * 2], bh[j * 2 + 1]);
        }
        if (s + 2 < 16)
            load_stage(s + 2, stage0 + (uint32_t)((s + 2) % NSTAGE) * STAGE_B, bm, bn, tid);
    }

    // epilogue: c0..c3 = (g,2t),(g,2t+1),(g+8,2t),(g+8,2t+1)
    const int g = lane >> 2, t2 = (lane & 3) * 2;
    #pragma unroll
    for (int i = 0; i < 2; i++) {
        const int row0 = bm + wm * 32 + i * 16 + g;
        #pragma unroll
        for (int j = 0; j < 4; j++) {
            const int colL = wn * 32 + j * 8 + t2;
            const int col = bn + colL;
            float2 v0 = { acc[i][j][0] + biasS[colL], acc[i][j][1] + biasS[colL + 1] };
            float2 v1 = { acc[i][j][2] + biasS[colL], acc[i][j][3] + biasS[colL + 1] };
            *(float2*)&g_qkv[(size_t)row0 * QC + col] = v0;
            *(float2*)&g_qkv[(size_t)(row0 + 8) * QC + col] = v1;
        }
    }
}

// ============================================================
// K2: split-K partials of S_h = K_h^T V_h (qsum moved out), float4 LDS.
// ============================================================
__global__ __launch_bounds__(256) void k_kv_outer()
{
    __shared__ float Ks[64][64];
    __shared__ float Vs[64][64];
    const int h = blockIdx.y;
    const int cidx = blockIdx.x;
    const int n0 = cidx * 64;
    const int tid = threadIdx.x;

    #pragma unroll
    for (int it = 0; it < 4; it++) {
        int s = tid + it * 256;
        int n = s >> 4, dv = (s & 15) * 4;
        const float* row = &g_qkv[(n0 + n) * QC + h * DH];
        *(float4*)&Ks[n][dv] = *(const float4*)(row + EMB + dv);
        *(float4*)&Vs[n][dv] = *(const float4*)(row + 2 * EMB + dv);
    }
    __syncthreads();

    const int ty = tid >> 4, tx = tid & 15;
    const int d1 = ty * 4, d2 = tx * 4;
    float acc[4][4] = {};
    #pragma unroll 4
    for (int n = 0; n < 64; n++) {
        float4 a = *(const float4*)&Ks[n][d1];
        float4 b = *(const float4*)&Vs[n][d2];
        float av[4] = {a.x, a.y, a.z, a.w};
        float bv[4] = {b.x, b.y, b.z, b.w};
        #pragma unroll
        for (int i = 0; i < 4; i++)
            #pragma unroll
            for (int j = 0; j < 4; j++)
                acc[i][j] += av[i] * bv[j];
    }
    float* Sout = &g_Spart[cidx * (NH * DH * DH) + h * (DH * DH)];
    #pragma unroll
    for (int i = 0; i < 4; i++)
        *(float4*)&Sout[(d1 + i) * DH + d2] =
            make_float4(acc[i][0], acc[i][1], acc[i][2], acc[i][3]);
}

// ============================================================
// K2a: coalesced partial column sums of Q (grid 2 x 64).
//   g_qsum_part[c][d] = sum of 64 rows of chunk c, column d.
// ============================================================
__global__ __launch_bounds__(256) void k_qsum_part()
{
    const int d = blockIdx.x * 256 + threadIdx.x;      // 0..511
    const int c = blockIdx.y;                          // 0..63
    const float* p = &g_qkv[(size_t)(c * 64) * QC + d];
    float s = 0.f;
    #pragma unroll 8
    for (int r = 0; r < 64; r++) s += p[(size_t)r * QC];
    g_qsum_part[c * (NH * DH) + d] = s;
}

__global__ __launch_bounds__(256) void k_reduce()
{
    int idx = blockIdx.x * 256 + threadIdx.x;
    if (idx < NH * DH * DH) {
        float s = 0.f;
        #pragma unroll 8
        for (int c = 0; c < 64; c++) s += g_Spart[c * (NH * DH * DH) + idx];
        g_S[idx] = s;
    } else if (idx < NH * DH * DH + NH * DH) {
        int o = idx - NH * DH * DH;
        float s = 0.f;
        #pragma unroll 8
        for (int c = 0; c < 64; c++) s += g_qsum_part[c * (NH * DH) + o];
        g_qsum[o] = s;
    }
}

// ============================================================
// K3: output = SCALE * Q @ S_h, 128-row tiles, transposed-Q smem,
//     8 rows x 4 cols per thread, row-paired fp32x2 FMA.
// ============================================================
__global__ __launch_bounds__(256) void k_out_gemm(float* __restrict__ out)
{
    __shared__ float Ss[64 * 64];       // [dk][d]
    __shared__ float Qt[64 * 128];      // [dk][n] transposed
    const int h = blockIdx.y;
    const int n0 = blockIdx.x * 128;
    const int tid = threadIdx.x;

    #pragma unroll
    for (int it = 0; it < 4; it++) {
        int s = tid + it * 256;
        *(float4*)&Ss[s * 4] = *(const float4*)&g_S[h * (DH * DH) + s * 4];
    }
    #pragma unroll
    for (int it = 0; it < 8; it++) {
        int s = tid + it * 256;          // 2048 slots: n(128) x dv4(16)
        int n = s & 127, d0 = (s >> 7) * 4;
        float4 v = *(const float4*)&g_qkv[(size_t)(n0 + n) * QC + h * DH + d0];
        Qt[(d0 + 0) * 128 + n] = v.x;
        Qt[(d0 + 1) * 128 + n] = v.y;
        Qt[(d0 + 2) * 128 + n] = v.z;
        Qt[(d0 + 3) * 128 + n] = v.w;
    }
    __syncthreads();

    const int ty = tid >> 4, tx = tid & 15;
    const int r0 = ty * 8, c0 = tx * 4;
    unsigned long long acc[4][4];
    #pragma unroll
    for (int i = 0; i < 4; i++)
        #pragma unroll
        for (int j = 0; j < 4; j++) acc[i][j] = 0ULL;

    #pragma unroll 4
    for (int k = 0; k < 64; k++) {
        unsigned long long a2[4];
        #pragma unroll
        for (int i = 0; i < 4; i++)
            a2[i] = *(const unsigned long long*)&Qt[k * 128 + r0 + 2 * i];
        float4 b = *(const float4*)&Ss[k * 64 + c0];
        unsigned int bu[4] = { __float_as_uint(b.x), __float_as_uint(b.y),
                               __float_as_uint(b.z), __float_as_uint(b.w) };
        unsigned long long bd[4];
        #pragma unroll
        for (int j = 0; j < 4; j++)
            asm("mov.b64 %0, {%1, %2};" : "=l"(bd[j]) : "r"(bu[j]), "r"(bu[j]));
        #pragma unroll
        for (int i = 0; i < 4; i++)
            #pragma unroll
            for (int j = 0; j < 4; j++)
                asm("fma.rn.f32x2 %0, %1, %2, %0;"
                    : "+l"(acc[i][j]) : "l"(a2[i]), "l"(bd[j]));
    }

    #pragma unroll
    for (int i = 0; i < 4; i++) {
        float lo[4], hi[4];
        #pragma unroll
        for (int j = 0; j < 4; j++) {
            unsigned int l, hb;
            asm("mov.b64 {%0, %1}, %2;" : "=r"(l), "=r"(hb) : "l"(acc[i][j]));
            lo[j] = __uint_as_float(l) * SCALE;
            hi[j] = __uint_as_float(hb) * SCALE;
        }
        float* o0 = out + (NH * NTOK) + h * (NTOK * DH)
                  + (size_t)(n0 + r0 + 2 * i) * DH + c0;
        *(float4*)(o0)      = make_float4(lo[0], lo[1], lo[2], lo[3]);
        *(float4*)(o0 + DH) = make_float4(hi[0], hi[1], hi[2], hi[3]);
    }
}

// ============================================================
// K4: coarse[h][n] = SCALE * dot(K[n,h,:], qsum[h,:])
// ============================================================
__global__ __launch_bounds__(256) void k_coarse(float* __restrict__ out)
{
    int idx = blockIdx.x * 256 + threadIdx.x;
    int h = idx >> 12, n = idx & (NTOK - 1);
    const float4* kp = (const float4*)&g_qkv[n * QC + EMB + h * DH];
    const float4* qp = (const float4*)&g_qsum[h * DH];
    float s = 0.f;
    #pragma unroll
    for (int v = 0; v < 16; v++) {
        float4 a = kp[v], b = qp[v];
        s += a.x * b.x + a.y * b.y + a.z * b.z + a.w * b.w;
    }
    out[idx] = s * SCALE;
}

// ============================================================
extern "C" void kernel_launch(void* const* d_in, const int* in_sizes, int n_in,
                              void* d_out, int out_size)
{
    const float* x = (const float*)d_in[0];   // [512][4096]
    const float* W = (const float*)d_in[1];   // [512][1536]
    const float* b = (const float*)d_in[2];   // [1536]
    float* out = (float*)d_out;               // [32768 coarse][2097152 output]

    static bool attr_done = false;
    if (!attr_done) {
        cudaFuncSetAttribute(k_qkv_tc, cudaFuncAttributeMaxDynamicSharedMemorySize, QTC_SMEM);
        attr_done = true;
    }

    k_splitX<<<dim3(128, 16), 256>>>(x);
    k_splitW<<<dim3(48, 16), 256>>>(W);
    k_qkv_tc<<<dim3(12, 64), 256, QTC_SMEM>>>(b);
    k_kv_outer<<<dim3(64, 8), 256>>>();
    k_qsum_part<<<dim3(2, 64), 256>>>();
    k_reduce<<<130, 256>>>();
    k_out_gemm<<<dim3(32, 8), 256>>>(out);
    k_coarse<<<128, 256>>>(out);
}